// round 15
// baseline (speedup 1.0000x reference)
#include <cuda_runtime.h>
#include <cuda_fp16.h>
#include <cstdint>
#include <math.h>

#define LQ   40000
#define DMOD 256
#define NH   8
#define NP   4
#define DH   32
#define HSP  200
#define WSP  200
#define GQ   8

// ---------------- scratch (no allocations allowed) ----------------
__device__ __half g_value[LQ * DMOD];     // value projection (fp16)
__device__ float  g_oa[LQ * 128];         // [off(64) | attn(32) | pad(32)] per query
__device__ __half g_sampled[LQ * DMOD];   // sampled output (fp16)
__device__ __half g_inp[LQ * DMOD];       // fp16 input_flatten
__device__ __half g_q16[LQ * DMOD];       // fp16 (query + query_pos)
__device__ __half g_wv[DMOD * DMOD];      // fp16 W_value
__device__ __half g_wout[DMOD * DMOD];    // fp16 W_out
__device__ __half g_woa[128 * DMOD];      // fp16 [W_off; W_attn; zeros]
__device__ float  g_boa[128];             // padded [b_off; b_attn; zeros]

// ---------------- helpers ----------------
__device__ __forceinline__ uint32_t h2_to_u32(__half2 h) {
    uint32_t u;
    memcpy(&u, &h, 4);
    return u;
}
__device__ __forceinline__ uint4 pack8(float4 a, float4 b) {
    uint4 o;
    o.x = h2_to_u32(__floats2half2_rn(a.x, a.y));
    o.y = h2_to_u32(__floats2half2_rn(a.z, a.w));
    o.z = h2_to_u32(__floats2half2_rn(b.x, b.y));
    o.w = h2_to_u32(__floats2half2_rn(b.z, b.w));
    return o;
}
__device__ __forceinline__ void mma16n8k16h(float* c, const uint32_t* a, const uint32_t* b) {
    asm volatile(
        "mma.sync.aligned.m16n8k16.row.col.f32.f16.f16.f32 "
        "{%0,%1,%2,%3}, {%4,%5,%6,%7}, {%8,%9}, {%0,%1,%2,%3};"
        : "+f"(c[0]), "+f"(c[1]), "+f"(c[2]), "+f"(c[3])
        : "r"(a[0]), "r"(a[1]), "r"(a[2]), "r"(a[3]), "r"(b[0]), "r"(b[1]));
}
__device__ __forceinline__ void ldsm4(uint32_t& r0, uint32_t& r1, uint32_t& r2,
                                      uint32_t& r3, uint32_t addr) {
    asm volatile("ldmatrix.sync.aligned.m8n8.x4.shared.b16 {%0,%1,%2,%3}, [%4];"
                 : "=r"(r0), "=r"(r1), "=r"(r2), "=r"(r3) : "r"(addr));
}
__device__ __forceinline__ void cp_async16(uint32_t dst, const void* src, uint32_t sz) {
    asm volatile("cp.async.cg.shared.global [%0], [%1], 16, %2;"
                 :: "r"(dst), "l"(src), "r"(sz));
}
__device__ __forceinline__ void cp_commit() {
    asm volatile("cp.async.commit_group;" ::: "memory");
}
__device__ __forceinline__ void cp_wait2() {
    asm volatile("cp.async.wait_group 2;" ::: "memory");
}

// ---------------- fused conversion: inp, (q+qpos), Wv, Wout -> fp16 ----------------
#define N8U (LQ * DMOD / 8)     // 1,280,000 units of 8 floats
#define W8U (DMOD * DMOD / 8)   // 8,192
__global__ void conv_fused(const float4* __restrict__ query, const float4* __restrict__ qpos,
                           const float4* __restrict__ inp, const float4* __restrict__ wv,
                           const float4* __restrict__ wout) {
    int i = blockIdx.x * blockDim.x + threadIdx.x;
    if (i < N8U) {
        float4 a = inp[i * 2], b = inp[i * 2 + 1];
        reinterpret_cast<uint4*>(g_inp)[i] = pack8(a, b);
    } else if (i < 2 * N8U) {
        int o = i - N8U;
        float4 a = query[o * 2], b = query[o * 2 + 1];
        float4 c = qpos[o * 2],  d = qpos[o * 2 + 1];
        a.x += c.x; a.y += c.y; a.z += c.z; a.w += c.w;
        b.x += d.x; b.y += d.y; b.z += d.z; b.w += d.w;
        reinterpret_cast<uint4*>(g_q16)[o] = pack8(a, b);
    } else if (i < 2 * N8U + W8U) {
        int o = i - 2 * N8U;
        reinterpret_cast<uint4*>(g_wv)[o] = pack8(wv[o * 2], wv[o * 2 + 1]);
    } else if (i < 2 * N8U + 2 * W8U) {
        int o = i - 2 * N8U - W8U;
        reinterpret_cast<uint4*>(g_wout)[o] = pack8(wout[o * 2], wout[o * 2 + 1]);
    }
}

// ---------------- pad [W_off; W_attn; 0] -> g_woa (fp16) + g_boa ----------------
__global__ void pad_woa(const float4* __restrict__ woff, const float4* __restrict__ wattn,
                        const float* __restrict__ boff, const float* __restrict__ battn) {
    if (blockIdx.x < 16) {
        int i = blockIdx.x * 256 + threadIdx.x;   // unit of 8 floats; 32 units/row
        int row = i >> 5, c8 = i & 31;
        float4 a, b;
        if (row < 64)      { a = woff[row * 64 + c8 * 2];          b = woff[row * 64 + c8 * 2 + 1]; }
        else if (row < 96) { a = wattn[(row - 64) * 64 + c8 * 2];  b = wattn[(row - 64) * 64 + c8 * 2 + 1]; }
        else               { a = make_float4(0, 0, 0, 0); b = a; }
        reinterpret_cast<uint4*>(g_woa)[i] = pack8(a, b);
    } else {
        int t = threadIdx.x;
        if (t < 128)
            g_boa[t] = t < 64 ? boff[t] : (t < 96 ? battn[t - 64] : 0.0f);
    }
}

// ============ shared fp16 GEMM body: 4-stage cp.async pipeline ============
__device__ __forceinline__ void gemm_body(const __half* __restrict__ A,
                                          const __half* __restrict__ B,
                                          const float* __restrict__ bias,
                                          __half* __restrict__ Ch, float* __restrict__ Cf,
                                          int bn, int N, int M) {
    constexpr int BM = 128, BK = 32, LD = 40;
    constexpr int NCHUNK = DMOD / BK;      // 8
    constexpr int ASZ = BM * LD;
    constexpr int SSZ = 2 * ASZ;

    extern __shared__ __half smh[];
    const uint32_t smem_u32 = (uint32_t)__cvta_generic_to_shared(smh);

    const int tid = threadIdx.x;
    const int wid = tid >> 5;
    const int lane = tid & 31;
    const int wm = wid & 3;
    const int wn = wid >> 2;
    const int bm = blockIdx.y * BM;
    const int lq = lane >> 2;
    const int lr = lane & 3;

    const int arow_l = wm * 32 + (lane & 15);
    const int acol_l = (lane >> 4) << 3;
    const int brow_l = wn * 64 + (lane & 7) + ((lane >> 4) << 3);
    const int bcol_l = ((lane >> 3) & 1) << 3;

    const int r0 = tid >> 2;
    const int f8 = (tid & 3) * 8;
    const __half* abase = A + (size_t)(bm + r0) * DMOD + f8;
    const __half* bbase = B + (size_t)(bn + r0) * DMOD + f8;
    uint32_t asz[2];
#pragma unroll
    for (int i = 0; i < 2; i++) asz[i] = (bm + r0 + 64 * i) < M ? 16u : 0u;

    auto issue_stage = [&](int buf, int k0) {
        const uint32_t sb = smem_u32 + (uint32_t)(buf * SSZ) * 2u;
#pragma unroll
        for (int i = 0; i < 2; i++)
            cp_async16(sb + (uint32_t)((r0 + 64 * i) * LD + f8) * 2u,
                       abase + k0 + (size_t)(64 * i) * DMOD, asz[i]);
#pragma unroll
        for (int i = 0; i < 2; i++)
            cp_async16(sb + (uint32_t)(ASZ + (r0 + 64 * i) * LD + f8) * 2u,
                       bbase + k0 + (size_t)(64 * i) * DMOD, 16u);
    };

    float acc[2][8][4];
#pragma unroll
    for (int i = 0; i < 2; i++)
#pragma unroll
        for (int j = 0; j < 8; j++)
#pragma unroll
            for (int r = 0; r < 4; r++) acc[i][j][r] = 0.0f;

    issue_stage(0, 0); cp_commit();
    issue_stage(1, BK); cp_commit();
    issue_stage(2, 2 * BK); cp_commit();

    for (int c = 0; c < NCHUNK; c++) {
        cp_wait2();
        __syncthreads();
        if (c + 3 < NCHUNK) issue_stage((c + 3) & 3, (c + 3) * BK);
        cp_commit();

        const uint32_t As_u = smem_u32 + (uint32_t)((c & 3) * SSZ) * 2u;
        const uint32_t Bs_u = As_u + (uint32_t)ASZ * 2u;
#pragma unroll
        for (int ks = 0; ks < 2; ks++) {
            const int kk = ks * 16;
            uint32_t a[2][4], b[4][4];
#pragma unroll
            for (int mi = 0; mi < 2; mi++)
                ldsm4(a[mi][0], a[mi][1], a[mi][2], a[mi][3],
                      As_u + (uint32_t)((arow_l + mi * 16) * LD + kk + acol_l) * 2u);
#pragma unroll
            for (int nb = 0; nb < 4; nb++)
                ldsm4(b[nb][0], b[nb][1], b[nb][2], b[nb][3],
                      Bs_u + (uint32_t)((brow_l + nb * 16) * LD + kk + bcol_l) * 2u);
#pragma unroll
            for (int mi = 0; mi < 2; mi++)
#pragma unroll
                for (int nb = 0; nb < 4; nb++) {
                    mma16n8k16h(acc[mi][nb * 2 + 0], a[mi], &b[nb][0]);
                    mma16n8k16h(acc[mi][nb * 2 + 1], a[mi], &b[nb][2]);
                }
        }
    }

#pragma unroll
    for (int mi = 0; mi < 2; mi++) {
        const int row0 = bm + wm * 32 + mi * 16 + lq;
#pragma unroll
        for (int ni = 0; ni < 8; ni++) {
            const int col = bn + wn * 64 + ni * 8 + lr * 2;
            const float bz0 = bias[col], bz1 = bias[col + 1];
            if (Cf) {
                if (row0 < M)
                    *reinterpret_cast<float2*>(Cf + (size_t)row0 * N + col) =
                        make_float2(acc[mi][ni][0] + bz0, acc[mi][ni][1] + bz1);
                if (row0 + 8 < M)
                    *reinterpret_cast<float2*>(Cf + (size_t)(row0 + 8) * N + col) =
                        make_float2(acc[mi][ni][2] + bz0, acc[mi][ni][3] + bz1);
            } else {
                if (row0 < M)
                    *reinterpret_cast<__half2*>(Ch + (size_t)row0 * N + col) =
                        __floats2half2_rn(acc[mi][ni][0] + bz0, acc[mi][ni][1] + bz1);
                if (row0 + 8 < M)
                    *reinterpret_cast<__half2*>(Ch + (size_t)(row0 + 8) * N + col) =
                        __floats2half2_rn(acc[mi][ni][2] + bz0, acc[mi][ni][3] + bz1);
            }
        }
    }
}

// ---- fused value + oa GEMM ----
__global__ __launch_bounds__(256, 2)
void valoa_gemm(const float* __restrict__ bv) {
    if (blockIdx.x < 2)
        gemm_body(g_inp, g_wv, bv, g_value, nullptr, blockIdx.x * 128, DMOD, LQ);
    else
        gemm_body(g_q16, g_woa, g_boa, nullptr, g_oa, 0, 128, LQ);
}

// ---- output GEMM ----
__global__ __launch_bounds__(256, 2)
void out_gemm(const float* __restrict__ bout, float* __restrict__ out) {
    gemm_body(g_sampled, g_wout, bout, nullptr, out, blockIdx.x * 128, DMOD, LQ);
}

// ---------------- sampler: scalar phase + dual-head half2 gather (LDS.128 pairs) ----------------
__global__ __launch_bounds__(256)
void sample_kernel(const float* __restrict__ refpts) {
    __shared__ __align__(16) int2 s_pc[256 * 4];   // (row idx, fp32 weight) per (q,h,p,corner)

    const int tid = threadIdx.x;
    const int q0 = blockIdx.x * GQ;
    const int qi = tid >> 5;
    const int h = (tid >> 2) & 7;
    const int p = tid & 3;
    const int q = q0 + qi;

    // ---- scalar phase: one thread per (q,h,p) ----
    const float refx = refpts[q * 2 + 0];
    const float refy = refpts[q * 2 + 1];
    const float* row = g_oa + (size_t)q * 128;
    const float lg = row[64 + h * 4 + p];
    const float ox = row[h * 8 + p * 2 + 0];
    const float oy = row[h * 8 + p * 2 + 1];

    float mx = lg;
    mx = fmaxf(mx, __shfl_xor_sync(0xFFFFFFFFu, mx, 1));
    mx = fmaxf(mx, __shfl_xor_sync(0xFFFFFFFFu, mx, 2));
    float e = expf(lg - mx);
    float s = e;
    s += __shfl_xor_sync(0xFFFFFFFFu, s, 1);
    s += __shfl_xor_sync(0xFFFFFFFFu, s, 2);
    const float ap = e / s;

    const float x = (refx + ox * (1.0f / WSP)) * WSP - 0.5f;
    const float y = (refy + oy * (1.0f / HSP)) * HSP - 0.5f;
    const float x0f = floorf(x), y0f = floorf(y);
    const int x0 = (int)x0f, y0 = (int)y0f;
    const float lw = x - x0f, lh = y - y0f;
    const int x1 = x0 + 1, y1 = y0 + 1;

    const float wc[4] = { (1.0f - lh) * (1.0f - lw), (1.0f - lh) * lw,
                          lh * (1.0f - lw),          lh * lw };
    const int xs[4] = { x0, x1, x0, x1 };
    const int ys[4] = { y0, y0, y1, y1 };
#pragma unroll
    for (int c = 0; c < 4; c++) {
        const bool v = (xs[c] >= 0) & (xs[c] < WSP) & (ys[c] >= 0) & (ys[c] < HSP);
        const float w = v ? ap * wc[c] : 0.0f;
        const int idx = v ? (ys[c] * WSP + xs[c]) : 0;
        s_pc[tid * 4 + c] = make_int2(idx, __float_as_int(w));
    }
    __syncthreads();

    // ---- gather phase: warp = query; lanes 0-15 head 2hh, lanes 16-31 head 2hh+1;
    //      each lane covers a channel PAIR via __half2; corners fetched 2-at-a-time via LDS.128 ----
    const int wid = tid >> 5, lane = tid & 31;
    const int half = lane >> 4;            // which head of the pair
    const int ci = lane & 15;              // channel-pair index (2*ci, 2*ci+1)
    const int gq = q0 + wid;

#pragma unroll
    for (int hh = 0; hh < 4; hh++) {
        const int head = hh * 2 + half;
        const __half2* vb = reinterpret_cast<const __half2*>(
            g_value + head * DH + ci * 2);
        const int sbase = (wid * 32 + head * 4) * 4;   // 16 corners for this head
        float ax = 0.0f, ay = 0.0f;
#pragma unroll
        for (int pc = 0; pc < 16; pc += 2) {
            int4 two = *reinterpret_cast<const int4*>(&s_pc[sbase + pc]);
            const float w0 = __int_as_float(two.y);
            const float w1 = __int_as_float(two.w);
            float2 v0 = __half22float2(vb[(size_t)two.x * (DMOD / 2)]);
            float2 v1 = __half22float2(vb[(size_t)two.z * (DMOD / 2)]);
            ax += w0 * v0.x + w1 * v1.x;
            ay += w0 * v0.y + w1 * v1.y;
        }
        *reinterpret_cast<__half2*>(
            g_sampled + (size_t)gq * DMOD + head * DH + ci * 2) =
            __floats2half2_rn(ax, ay);
    }
}

// ---------------- launch ----------------
extern "C" void kernel_launch(void* const* d_in, const int* in_sizes, int n_in,
                              void* d_out, int out_size) {
    const float* query  = (const float*)d_in[0];
    const float* qpos   = (const float*)d_in[1];
    const float* refpts = (const float*)d_in[2];
    const float* inp    = (const float*)d_in[3];
    const float* Wv     = (const float*)d_in[4];
    const float* bv     = (const float*)d_in[5];
    const float* Woff   = (const float*)d_in[6];
    const float* boff   = (const float*)d_in[7];
    const float* Wattn  = (const float*)d_in[8];
    const float* battn  = (const float*)d_in[9];
    const float* Wout   = (const float*)d_in[10];
    const float* bout   = (const float*)d_in[11];
    float* out = (float*)d_out;

    const int gy = (LQ + 127) / 128;  // 313
    const int SMEM_PIPE = 4 * (2 * 128 * 40) * 2;  // 81920
    cudaFuncSetAttribute(valoa_gemm, cudaFuncAttributeMaxDynamicSharedMemorySize, SMEM_PIPE);
    cudaFuncSetAttribute(out_gemm,   cudaFuncAttributeMaxDynamicSharedMemorySize, SMEM_PIPE);

    // 0. conversions
    {
        int total = 2 * N8U + 2 * W8U;
        conv_fused<<<(total + 255) / 256, 256>>>(
            (const float4*)query, (const float4*)qpos, (const float4*)inp,
            (const float4*)Wv, (const float4*)Wout);
        pad_woa<<<17, 256>>>((const float4*)Woff, (const float4*)Wattn, boff, battn);
    }

    // 1. fused: value projection (x<2) + [off|attn] projection (x==2)
    valoa_gemm<<<dim3(3, gy), 256, SMEM_PIPE>>>(bv);

    // 2. fused softmax + bilinear sampling
    sample_kernel<<<LQ / GQ, 256>>>(refpts);

    // 3. out = sampled @ W_out^T + b_out
    out_gemm<<<dim3(2, gy), 256, SMEM_PIPE>>>(bout, out);
}

// round 16
// speedup vs baseline: 1.0414x; 1.0414x over previous
#include <cuda_runtime.h>
#include <cuda_fp16.h>
#include <cstdint>
#include <math.h>

#define LQ   40000
#define DMOD 256
#define NH   8
#define NP   4
#define DH   32
#define HSP  200
#define WSP  200
#define GQ   8

// ---------------- scratch (no allocations allowed) ----------------
__device__ __half g_value[LQ * DMOD];     // value projection (fp16)
__device__ float  g_oa[LQ * 128];         // [off(64) | attn(32) | pad(32)] per query
__device__ __half g_sampled[LQ * DMOD];   // sampled output (fp16)
__device__ __half g_inp[LQ * DMOD];       // fp16 input_flatten
__device__ __half g_wv[DMOD * DMOD];      // fp16 W_value
__device__ __half g_wout[DMOD * DMOD];    // fp16 W_out
__device__ __half g_woa[128 * DMOD];      // fp16 [W_off; W_attn; zeros]
__device__ float  g_boa[128];             // padded [b_off; b_attn; zeros]

// ---------------- helpers ----------------
__device__ __forceinline__ uint32_t h2_to_u32(__half2 h) {
    uint32_t u;
    memcpy(&u, &h, 4);
    return u;
}
__device__ __forceinline__ uint4 pack8(float4 a, float4 b) {
    uint4 o;
    o.x = h2_to_u32(__floats2half2_rn(a.x, a.y));
    o.y = h2_to_u32(__floats2half2_rn(a.z, a.w));
    o.z = h2_to_u32(__floats2half2_rn(b.x, b.y));
    o.w = h2_to_u32(__floats2half2_rn(b.z, b.w));
    return o;
}
__device__ __forceinline__ void mma16n8k16h(float* c, const uint32_t* a, const uint32_t* b) {
    asm volatile(
        "mma.sync.aligned.m16n8k16.row.col.f32.f16.f16.f32 "
        "{%0,%1,%2,%3}, {%4,%5,%6,%7}, {%8,%9}, {%0,%1,%2,%3};"
        : "+f"(c[0]), "+f"(c[1]), "+f"(c[2]), "+f"(c[3])
        : "r"(a[0]), "r"(a[1]), "r"(a[2]), "r"(a[3]), "r"(b[0]), "r"(b[1]));
}
__device__ __forceinline__ void ldsm4(uint32_t& r0, uint32_t& r1, uint32_t& r2,
                                      uint32_t& r3, uint32_t addr) {
    asm volatile("ldmatrix.sync.aligned.m8n8.x4.shared.b16 {%0,%1,%2,%3}, [%4];"
                 : "=r"(r0), "=r"(r1), "=r"(r2), "=r"(r3) : "r"(addr));
}
__device__ __forceinline__ void cp_async16(uint32_t dst, const void* src, uint32_t sz) {
    asm volatile("cp.async.cg.shared.global [%0], [%1], 16, %2;"
                 :: "r"(dst), "l"(src), "r"(sz));
}
__device__ __forceinline__ void cp_commit() {
    asm volatile("cp.async.commit_group;" ::: "memory");
}
__device__ __forceinline__ void cp_wait2() {
    asm volatile("cp.async.wait_group 2;" ::: "memory");
}
__device__ __forceinline__ void cp_wait0() {
    asm volatile("cp.async.wait_group 0;" ::: "memory");
}

// ---------------- fused conversion: inp, Wv, Wout -> fp16 ; pad woa + boa ----------------
#define N8U (LQ * DMOD / 8)     // 1,280,000 units of 8 floats
#define W8U (DMOD * DMOD / 8)   // 8,192
#define CB1 (N8U + W8U)
#define CB2 (N8U + 2 * W8U)
#define CB3 (CB2 + 4096)        // woa: 128*256/8
#define CB4 (CB3 + 128)         // boa
__global__ void conv_fused(const float4* __restrict__ inp, const float4* __restrict__ wv,
                           const float4* __restrict__ wout,
                           const float4* __restrict__ woff, const float4* __restrict__ wattn,
                           const float* __restrict__ boff, const float* __restrict__ battn) {
    int i = blockIdx.x * blockDim.x + threadIdx.x;
    if (i < N8U) {
        reinterpret_cast<uint4*>(g_inp)[i] = pack8(inp[i * 2], inp[i * 2 + 1]);
    } else if (i < CB1) {
        int o = i - N8U;
        reinterpret_cast<uint4*>(g_wv)[o] = pack8(wv[o * 2], wv[o * 2 + 1]);
    } else if (i < CB2) {
        int o = i - CB1;
        reinterpret_cast<uint4*>(g_wout)[o] = pack8(wout[o * 2], wout[o * 2 + 1]);
    } else if (i < CB3) {
        int o = i - CB2;                 // unit of 8 halves; 32 units/row
        int row = o >> 5, c8 = o & 31;
        float4 a, b;
        if (row < 64)      { a = woff[row * 64 + c8 * 2];         b = woff[row * 64 + c8 * 2 + 1]; }
        else if (row < 96) { a = wattn[(row - 64) * 64 + c8 * 2]; b = wattn[(row - 64) * 64 + c8 * 2 + 1]; }
        else               { a = make_float4(0, 0, 0, 0); b = a; }
        reinterpret_cast<uint4*>(g_woa)[o] = pack8(a, b);
    } else if (i < CB4) {
        int t = i - CB3;
        g_boa[t] = t < 64 ? boff[t] : (t < 96 ? battn[t - 64] : 0.0f);
    }
}

// ============ shared fp16 GEMM body: 4-stage cp.async pipeline ============
__device__ __forceinline__ void gemm_body(const __half* __restrict__ A,
                                          const __half* __restrict__ B,
                                          const float* __restrict__ bias,
                                          __half* __restrict__ Ch, float* __restrict__ Cf,
                                          int bn, int N, int M) {
    constexpr int BM = 128, BK = 32, LD = 40;
    constexpr int NCHUNK = DMOD / BK;      // 8
    constexpr int ASZ = BM * LD;
    constexpr int SSZ = 2 * ASZ;

    extern __shared__ __half smh[];
    const uint32_t smem_u32 = (uint32_t)__cvta_generic_to_shared(smh);

    const int tid = threadIdx.x;
    const int wid = tid >> 5;
    const int lane = tid & 31;
    const int wm = wid & 3;
    const int wn = wid >> 2;
    const int bm = blockIdx.y * BM;
    const int lq = lane >> 2;
    const int lr = lane & 3;

    const int arow_l = wm * 32 + (lane & 15);
    const int acol_l = (lane >> 4) << 3;
    const int brow_l = wn * 64 + (lane & 7) + ((lane >> 4) << 3);
    const int bcol_l = ((lane >> 3) & 1) << 3;

    const int r0 = tid >> 2;
    const int f8 = (tid & 3) * 8;
    const __half* abase = A + (size_t)(bm + r0) * DMOD + f8;
    const __half* bbase = B + (size_t)(bn + r0) * DMOD + f8;
    uint32_t asz[2];
#pragma unroll
    for (int i = 0; i < 2; i++) asz[i] = (bm + r0 + 64 * i) < M ? 16u : 0u;

    auto issue_stage = [&](int buf, int k0) {
        const uint32_t sb = smem_u32 + (uint32_t)(buf * SSZ) * 2u;
#pragma unroll
        for (int i = 0; i < 2; i++)
            cp_async16(sb + (uint32_t)((r0 + 64 * i) * LD + f8) * 2u,
                       abase + k0 + (size_t)(64 * i) * DMOD, asz[i]);
#pragma unroll
        for (int i = 0; i < 2; i++)
            cp_async16(sb + (uint32_t)(ASZ + (r0 + 64 * i) * LD + f8) * 2u,
                       bbase + k0 + (size_t)(64 * i) * DMOD, 16u);
    };

    float acc[2][8][4];
#pragma unroll
    for (int i = 0; i < 2; i++)
#pragma unroll
        for (int j = 0; j < 8; j++)
#pragma unroll
            for (int r = 0; r < 4; r++) acc[i][j][r] = 0.0f;

    issue_stage(0, 0); cp_commit();
    issue_stage(1, BK); cp_commit();
    issue_stage(2, 2 * BK); cp_commit();

    for (int c = 0; c < NCHUNK; c++) {
        cp_wait2();
        __syncthreads();
        if (c + 3 < NCHUNK) issue_stage((c + 3) & 3, (c + 3) * BK);
        cp_commit();

        const uint32_t As_u = smem_u32 + (uint32_t)((c & 3) * SSZ) * 2u;
        const uint32_t Bs_u = As_u + (uint32_t)ASZ * 2u;
#pragma unroll
        for (int ks = 0; ks < 2; ks++) {
            const int kk = ks * 16;
            uint32_t a[2][4], b[4][4];
#pragma unroll
            for (int mi = 0; mi < 2; mi++)
                ldsm4(a[mi][0], a[mi][1], a[mi][2], a[mi][3],
                      As_u + (uint32_t)((arow_l + mi * 16) * LD + kk + acol_l) * 2u);
#pragma unroll
            for (int nb = 0; nb < 4; nb++)
                ldsm4(b[nb][0], b[nb][1], b[nb][2], b[nb][3],
                      Bs_u + (uint32_t)((brow_l + nb * 16) * LD + kk + bcol_l) * 2u);
#pragma unroll
            for (int mi = 0; mi < 2; mi++)
#pragma unroll
                for (int nb = 0; nb < 4; nb++) {
                    mma16n8k16h(acc[mi][nb * 2 + 0], a[mi], &b[nb][0]);
                    mma16n8k16h(acc[mi][nb * 2 + 1], a[mi], &b[nb][2]);
                }
        }
    }

#pragma unroll
    for (int mi = 0; mi < 2; mi++) {
        const int row0 = bm + wm * 32 + mi * 16 + lq;
#pragma unroll
        for (int ni = 0; ni < 8; ni++) {
            const int col = bn + wn * 64 + ni * 8 + lr * 2;
            const float bz0 = bias[col], bz1 = bias[col + 1];
            if (Cf) {
                if (row0 < M)
                    *reinterpret_cast<float2*>(Cf + (size_t)row0 * N + col) =
                        make_float2(acc[mi][ni][0] + bz0, acc[mi][ni][1] + bz1);
                if (row0 + 8 < M)
                    *reinterpret_cast<float2*>(Cf + (size_t)(row0 + 8) * N + col) =
                        make_float2(acc[mi][ni][2] + bz0, acc[mi][ni][3] + bz1);
            } else {
                if (row0 < M)
                    *reinterpret_cast<__half2*>(Ch + (size_t)row0 * N + col) =
                        __floats2half2_rn(acc[mi][ni][0] + bz0, acc[mi][ni][1] + bz1);
                if (row0 + 8 < M)
                    *reinterpret_cast<__half2*>(Ch + (size_t)(row0 + 8) * N + col) =
                        __floats2half2_rn(acc[mi][ni][2] + bz0, acc[mi][ni][3] + bz1);
            }
        }
    }
}

// ============ oa GEMM body: fp32 q/qpos via cp.async staging, fused add+cvt ============
// smem layout (bytes from base): A tile fp16 [0,10240); B stages [10240,30720);
// q fp32 [30720,49152); qpos fp32 [49152,67584)
__device__ __forceinline__ void gemm_body_oa(const float* __restrict__ q,
                                             const float* __restrict__ qp) {
    constexpr int BM = 128, BK = 32, LDH = 40, LDF = 36;
    constexpr int NCHUNK = DMOD / BK;

    extern __shared__ __half smh[];
    char* sbase = reinterpret_cast<char*>(smh);
    const uint32_t su = (uint32_t)__cvta_generic_to_shared(smh);
    const uint32_t A_u = su;
    const uint32_t B_u = su + 10240;
    const uint32_t QF_u = su + 30720;
    const uint32_t QP_u = su + 49152;

    const int tid = threadIdx.x;
    const int wid = tid >> 5;
    const int lane = tid & 31;
    const int wm = wid & 3;
    const int wn = wid >> 2;
    const int bm = blockIdx.y * BM;
    const int lq = lane >> 2;
    const int lr = lane & 3;

    const int arow_l = wm * 32 + (lane & 15);
    const int acol_l = (lane >> 4) << 3;
    const int brow_l = wn * 64 + (lane & 7) + ((lane >> 4) << 3);
    const int bcol_l = ((lane >> 3) & 1) << 3;

    auto issue_chunk = [&](int k0, int bbuf) {
#pragma unroll
        for (int i = 0; i < 4; i++) {
            int idx = tid + i * 256;
            int row = idx >> 3, f4 = (idx & 7) * 4;
            int gr = bm + row;
            uint32_t sz = gr < LQ ? 16u : 0u;
            gr = gr < LQ ? gr : LQ - 1;
            cp_async16(QF_u + (uint32_t)(row * LDF + f4) * 4u,
                       q + (size_t)gr * DMOD + k0 + f4, sz);
            cp_async16(QP_u + (uint32_t)(row * LDF + f4) * 4u,
                       qp + (size_t)gr * DMOD + k0 + f4, sz);
        }
#pragma unroll
        for (int i = 0; i < 2; i++) {
            int idx = tid + i * 256;
            int row = idx >> 2, f8 = (idx & 3) * 8;
            cp_async16(B_u + (uint32_t)(bbuf * 10240) + (uint32_t)(row * LDH + f8) * 2u,
                       g_woa + (size_t)row * DMOD + k0 + f8, 16u);
        }
        cp_commit();
    };

    float acc[2][8][4];
#pragma unroll
    for (int i = 0; i < 2; i++)
#pragma unroll
        for (int j = 0; j < 8; j++)
#pragma unroll
            for (int r = 0; r < 4; r++) acc[i][j][r] = 0.0f;

    issue_chunk(0, 0);

    for (int c = 0; c < NCHUNK; c++) {
        cp_wait0();
        __syncthreads();
        // convert q+qpos (fp32 smem) -> fp16 A tile
        const float* qf = reinterpret_cast<const float*>(sbase + 30720);
        const float* qpf = reinterpret_cast<const float*>(sbase + 49152);
#pragma unroll
        for (int i = 0; i < 2; i++) {
            int g = tid + i * 256;
            int row = g >> 2, f8 = (g & 3) * 8;
            const float* a = qf + row * LDF + f8;
            const float* b = qpf + row * LDF + f8;
            float4 a0 = *reinterpret_cast<const float4*>(a);
            float4 a1 = *reinterpret_cast<const float4*>(a + 4);
            float4 b0 = *reinterpret_cast<const float4*>(b);
            float4 b1 = *reinterpret_cast<const float4*>(b + 4);
            a0.x += b0.x; a0.y += b0.y; a0.z += b0.z; a0.w += b0.w;
            a1.x += b1.x; a1.y += b1.y; a1.z += b1.z; a1.w += b1.w;
            *reinterpret_cast<uint4*>(sbase + (row * LDH + f8) * 2) = pack8(a0, a1);
        }
        __syncthreads();
        if (c + 1 < NCHUNK) issue_chunk((c + 1) * BK, (c + 1) & 1);

        const uint32_t Bs_u = B_u + (uint32_t)((c & 1) * 10240);
#pragma unroll
        for (int ks = 0; ks < 2; ks++) {
            const int kk = ks * 16;
            uint32_t a[2][4], b[4][4];
#pragma unroll
            for (int mi = 0; mi < 2; mi++)
                ldsm4(a[mi][0], a[mi][1], a[mi][2], a[mi][3],
                      A_u + (uint32_t)((arow_l + mi * 16) * LDH + kk + acol_l) * 2u);
#pragma unroll
            for (int nb = 0; nb < 4; nb++)
                ldsm4(b[nb][0], b[nb][1], b[nb][2], b[nb][3],
                      Bs_u + (uint32_t)((brow_l + nb * 16) * LDH + kk + bcol_l) * 2u);
#pragma unroll
            for (int mi = 0; mi < 2; mi++)
#pragma unroll
                for (int nb = 0; nb < 4; nb++) {
                    mma16n8k16h(acc[mi][nb * 2 + 0], a[mi], &b[nb][0]);
                    mma16n8k16h(acc[mi][nb * 2 + 1], a[mi], &b[nb][2]);
                }
        }
    }

#pragma unroll
    for (int mi = 0; mi < 2; mi++) {
        const int row0 = bm + wm * 32 + mi * 16 + lq;
#pragma unroll
        for (int ni = 0; ni < 8; ni++) {
            const int col = wn * 64 + ni * 8 + lr * 2;
            const float bz0 = g_boa[col], bz1 = g_boa[col + 1];
            if (row0 < LQ)
                *reinterpret_cast<float2*>(g_oa + (size_t)row0 * 128 + col) =
                    make_float2(acc[mi][ni][0] + bz0, acc[mi][ni][1] + bz1);
            if (row0 + 8 < LQ)
                *reinterpret_cast<float2*>(g_oa + (size_t)(row0 + 8) * 128 + col) =
                    make_float2(acc[mi][ni][2] + bz0, acc[mi][ni][3] + bz1);
        }
    }
}

// ---- fused value + oa GEMM ----
__global__ __launch_bounds__(256, 2)
void valoa_gemm(const float* __restrict__ bv, const float* __restrict__ q,
                const float* __restrict__ qp) {
    if (blockIdx.x < 2)
        gemm_body(g_inp, g_wv, bv, g_value, nullptr, blockIdx.x * 128, DMOD, LQ);
    else
        gemm_body_oa(q, qp);
}

// ---- output GEMM ----
__global__ __launch_bounds__(256, 2)
void out_gemm(const float* __restrict__ bout, float* __restrict__ out) {
    gemm_body(g_sampled, g_wout, bout, nullptr, out, blockIdx.x * 128, DMOD, LQ);
}

// ---------------- sampler: scalar phase + dual-head half2 gather (round-14 version) ----------------
__global__ __launch_bounds__(256)
void sample_kernel(const float* __restrict__ refpts) {
    __shared__ int2 s_pc[256 * 4];   // (row idx, fp32 weight) per (q,h,p,corner)

    const int tid = threadIdx.x;
    const int q0 = blockIdx.x * GQ;
    const int qi = tid >> 5;
    const int h = (tid >> 2) & 7;
    const int p = tid & 3;
    const int q = q0 + qi;

    const float refx = refpts[q * 2 + 0];
    const float refy = refpts[q * 2 + 1];
    const float* row = g_oa + (size_t)q * 128;
    const float lg = row[64 + h * 4 + p];
    const float ox = row[h * 8 + p * 2 + 0];
    const float oy = row[h * 8 + p * 2 + 1];

    float mx = lg;
    mx = fmaxf(mx, __shfl_xor_sync(0xFFFFFFFFu, mx, 1));
    mx = fmaxf(mx, __shfl_xor_sync(0xFFFFFFFFu, mx, 2));
    float e = expf(lg - mx);
    float s = e;
    s += __shfl_xor_sync(0xFFFFFFFFu, s, 1);
    s += __shfl_xor_sync(0xFFFFFFFFu, s, 2);
    const float ap = e / s;

    const float x = (refx + ox * (1.0f / WSP)) * WSP - 0.5f;
    const float y = (refy + oy * (1.0f / HSP)) * HSP - 0.5f;
    const float x0f = floorf(x), y0f = floorf(y);
    const int x0 = (int)x0f, y0 = (int)y0f;
    const float lw = x - x0f, lh = y - y0f;
    const int x1 = x0 + 1, y1 = y0 + 1;

    const float wc[4] = { (1.0f - lh) * (1.0f - lw), (1.0f - lh) * lw,
                          lh * (1.0f - lw),          lh * lw };
    const int xs[4] = { x0, x1, x0, x1 };
    const int ys[4] = { y0, y0, y1, y1 };
#pragma unroll
    for (int c = 0; c < 4; c++) {
        const bool v = (xs[c] >= 0) & (xs[c] < WSP) & (ys[c] >= 0) & (ys[c] < HSP);
        const float w = v ? ap * wc[c] : 0.0f;
        const int idx = v ? (ys[c] * WSP + xs[c]) : 0;
        s_pc[tid * 4 + c] = make_int2(idx, __float_as_int(w));
    }
    __syncthreads();

    const int wid = tid >> 5, lane = tid & 31;
    const int half = lane >> 4;            // which head of the pair
    const int ci = lane & 15;              // channel-pair index
    const int gq = q0 + wid;

#pragma unroll
    for (int hh = 0; hh < 4; hh++) {
        const int head = hh * 2 + half;
        const __half2* vb = reinterpret_cast<const __half2*>(
            g_value + head * DH + ci * 2);
        const int sbase = (wid * 32 + head * 4) * 4;
        float ax = 0.0f, ay = 0.0f;
#pragma unroll
        for (int pc = 0; pc < 16; pc++) {
            int2 ew = s_pc[sbase + pc];
            const float w = __int_as_float(ew.y);
            float2 vf = __half22float2(vb[(size_t)ew.x * (DMOD / 2)]);
            ax += w * vf.x;
            ay += w * vf.y;
        }
        *reinterpret_cast<__half2*>(
            g_sampled + (size_t)gq * DMOD + head * DH + ci * 2) =
            __floats2half2_rn(ax, ay);
    }
}

// ---------------- launch ----------------
extern "C" void kernel_launch(void* const* d_in, const int* in_sizes, int n_in,
                              void* d_out, int out_size) {
    const float* query  = (const float*)d_in[0];
    const float* qpos   = (const float*)d_in[1];
    const float* refpts = (const float*)d_in[2];
    const float* inp    = (const float*)d_in[3];
    const float* Wv     = (const float*)d_in[4];
    const float* bv     = (const float*)d_in[5];
    const float* Woff   = (const float*)d_in[6];
    const float* boff   = (const float*)d_in[7];
    const float* Wattn  = (const float*)d_in[8];
    const float* battn  = (const float*)d_in[9];
    const float* Wout   = (const float*)d_in[10];
    const float* bout   = (const float*)d_in[11];
    float* out = (float*)d_out;

    const int gy = (LQ + 127) / 128;  // 313
    const int SMEM_PIPE = 4 * (2 * 128 * 40) * 2;  // 81920 (oa branch uses 67584 of it)
    cudaFuncSetAttribute(valoa_gemm, cudaFuncAttributeMaxDynamicSharedMemorySize, SMEM_PIPE);
    cudaFuncSetAttribute(out_gemm,   cudaFuncAttributeMaxDynamicSharedMemorySize, SMEM_PIPE);

    // 0. fused conversions: inp/Wv/Wout -> fp16, pad woa + boa  (q NOT converted)
    conv_fused<<<(CB4 + 255) / 256, 256>>>(
        (const float4*)inp, (const float4*)Wv, (const float4*)Wout,
        (const float4*)Woff, (const float4*)Wattn, boff, battn);

    // 1. fused: value projection (x<2) + oa projection (x==2, fp32 q via cp.async)
    valoa_gemm<<<dim3(3, gy), 256, SMEM_PIPE>>>(bv, query, qpos);

    // 2. fused softmax + bilinear sampling
    sample_kernel<<<LQ / GQ, 256>>>(refpts);

    // 3. out = sampled @ W_out^T + b_out
    out_gemm<<<dim3(2, gy), 256, SMEM_PIPE>>>(bout, out);
}

// round 17
// speedup vs baseline: 1.0417x; 1.0003x over previous
#include <cuda_runtime.h>
#include <cuda_fp16.h>
#include <cstdint>
#include <math.h>

#define LQ   40000
#define DMOD 256
#define NH   8
#define NP   4
#define DH   32
#define HSP  200
#define WSP  200
#define GQ   8

// ---------------- scratch (no allocations allowed) ----------------
__device__ __half g_value[LQ * DMOD];     // value projection (fp16)
__device__ float  g_oa[LQ * 128];         // [off(64) | attn(32) | pad(32)] per query
__device__ __half g_sampled[LQ * DMOD];   // sampled output (fp16)
__device__ __half g_wv[DMOD * DMOD];      // fp16 W_value
__device__ __half g_wout[DMOD * DMOD];    // fp16 W_out
__device__ __half g_woa[128 * DMOD];      // fp16 [W_off; W_attn; zeros]
__device__ float  g_boa[128];             // padded [b_off; b_attn; zeros]

// ---------------- helpers ----------------
__device__ __forceinline__ uint32_t h2_to_u32(__half2 h) {
    uint32_t u;
    memcpy(&u, &h, 4);
    return u;
}
__device__ __forceinline__ uint4 pack8(float4 a, float4 b) {
    uint4 o;
    o.x = h2_to_u32(__floats2half2_rn(a.x, a.y));
    o.y = h2_to_u32(__floats2half2_rn(a.z, a.w));
    o.z = h2_to_u32(__floats2half2_rn(b.x, b.y));
    o.w = h2_to_u32(__floats2half2_rn(b.z, b.w));
    return o;
}
__device__ __forceinline__ void mma16n8k16h(float* c, const uint32_t* a, const uint32_t* b) {
    asm volatile(
        "mma.sync.aligned.m16n8k16.row.col.f32.f16.f16.f32 "
        "{%0,%1,%2,%3}, {%4,%5,%6,%7}, {%8,%9}, {%0,%1,%2,%3};"
        : "+f"(c[0]), "+f"(c[1]), "+f"(c[2]), "+f"(c[3])
        : "r"(a[0]), "r"(a[1]), "r"(a[2]), "r"(a[3]), "r"(b[0]), "r"(b[1]));
}
__device__ __forceinline__ void ldsm4(uint32_t& r0, uint32_t& r1, uint32_t& r2,
                                      uint32_t& r3, uint32_t addr) {
    asm volatile("ldmatrix.sync.aligned.m8n8.x4.shared.b16 {%0,%1,%2,%3}, [%4];"
                 : "=r"(r0), "=r"(r1), "=r"(r2), "=r"(r3) : "r"(addr));
}
__device__ __forceinline__ void cp_async16(uint32_t dst, const void* src, uint32_t sz) {
    asm volatile("cp.async.cg.shared.global [%0], [%1], 16, %2;"
                 :: "r"(dst), "l"(src), "r"(sz));
}
__device__ __forceinline__ void cp_commit() {
    asm volatile("cp.async.commit_group;" ::: "memory");
}
__device__ __forceinline__ void cp_wait2() {
    asm volatile("cp.async.wait_group 2;" ::: "memory");
}
__device__ __forceinline__ void cp_wait1() {
    asm volatile("cp.async.wait_group 1;" ::: "memory");
}
__device__ __forceinline__ void cp_wait0() {
    asm volatile("cp.async.wait_group 0;" ::: "memory");
}

// ---------------- weights-only conversion: Wv, Wout -> fp16 ; pad woa + boa ----------------
#define W8U (DMOD * DMOD / 8)   // 8,192
#define KB1 (2 * W8U)
#define KB2 (KB1 + 4096)        // woa: 128*256/8
#define KB3 (KB2 + 128)         // boa
__global__ void conv_w(const float4* __restrict__ wv, const float4* __restrict__ wout,
                       const float4* __restrict__ woff, const float4* __restrict__ wattn,
                       const float* __restrict__ boff, const float* __restrict__ battn) {
    int i = blockIdx.x * blockDim.x + threadIdx.x;
    if (i < W8U) {
        reinterpret_cast<uint4*>(g_wv)[i] = pack8(wv[i * 2], wv[i * 2 + 1]);
    } else if (i < KB1) {
        int o = i - W8U;
        reinterpret_cast<uint4*>(g_wout)[o] = pack8(wout[o * 2], wout[o * 2 + 1]);
    } else if (i < KB2) {
        int o = i - KB1;                 // unit of 8 halves; 32 units/row
        int row = o >> 5, c8 = o & 31;
        float4 a, b;
        if (row < 64)      { a = woff[row * 64 + c8 * 2];         b = woff[row * 64 + c8 * 2 + 1]; }
        else if (row < 96) { a = wattn[(row - 64) * 64 + c8 * 2]; b = wattn[(row - 64) * 64 + c8 * 2 + 1]; }
        else               { a = make_float4(0, 0, 0, 0); b = a; }
        reinterpret_cast<uint4*>(g_woa)[o] = pack8(a, b);
    } else if (i < KB3) {
        int t = i - KB1 - 4096;
        g_boa[t] = t < 64 ? boff[t] : (t < 96 ? battn[t - 64] : 0.0f);
    }
}

// ============ fp16 GEMM body (fp16 A in gmem): 4-stage cp.async pipeline ============
__device__ __forceinline__ void gemm_body(const __half* __restrict__ A,
                                          const __half* __restrict__ B,
                                          const float* __restrict__ bias,
                                          __half* __restrict__ Ch, float* __restrict__ Cf,
                                          int bn, int N, int M) {
    constexpr int BM = 128, BK = 32, LD = 40;
    constexpr int NCHUNK = DMOD / BK;      // 8
    constexpr int ASZ = BM * LD;
    constexpr int SSZ = 2 * ASZ;

    extern __shared__ __half smh[];
    const uint32_t smem_u32 = (uint32_t)__cvta_generic_to_shared(smh);

    const int tid = threadIdx.x;
    const int wid = tid >> 5;
    const int lane = tid & 31;
    const int wm = wid & 3;
    const int wn = wid >> 2;
    const int bm = blockIdx.y * BM;
    const int lq = lane >> 2;
    const int lr = lane & 3;

    const int arow_l = wm * 32 + (lane & 15);
    const int acol_l = (lane >> 4) << 3;
    const int brow_l = wn * 64 + (lane & 7) + ((lane >> 4) << 3);
    const int bcol_l = ((lane >> 3) & 1) << 3;

    const int r0 = tid >> 2;
    const int f8 = (tid & 3) * 8;
    const __half* abase = A + (size_t)(bm + r0) * DMOD + f8;
    const __half* bbase = B + (size_t)(bn + r0) * DMOD + f8;
    uint32_t asz[2];
#pragma unroll
    for (int i = 0; i < 2; i++) asz[i] = (bm + r0 + 64 * i) < M ? 16u : 0u;

    auto issue_stage = [&](int buf, int k0) {
        const uint32_t sb = smem_u32 + (uint32_t)(buf * SSZ) * 2u;
#pragma unroll
        for (int i = 0; i < 2; i++)
            cp_async16(sb + (uint32_t)((r0 + 64 * i) * LD + f8) * 2u,
                       abase + k0 + (size_t)(64 * i) * DMOD, asz[i]);
#pragma unroll
        for (int i = 0; i < 2; i++)
            cp_async16(sb + (uint32_t)(ASZ + (r0 + 64 * i) * LD + f8) * 2u,
                       bbase + k0 + (size_t)(64 * i) * DMOD, 16u);
    };

    float acc[2][8][4];
#pragma unroll
    for (int i = 0; i < 2; i++)
#pragma unroll
        for (int j = 0; j < 8; j++)
#pragma unroll
            for (int r = 0; r < 4; r++) acc[i][j][r] = 0.0f;

    issue_stage(0, 0); cp_commit();
    issue_stage(1, BK); cp_commit();
    issue_stage(2, 2 * BK); cp_commit();

    for (int c = 0; c < NCHUNK; c++) {
        cp_wait2();
        __syncthreads();
        if (c + 3 < NCHUNK) issue_stage((c + 3) & 3, (c + 3) * BK);
        cp_commit();

        const uint32_t As_u = smem_u32 + (uint32_t)((c & 3) * SSZ) * 2u;
        const uint32_t Bs_u = As_u + (uint32_t)ASZ * 2u;
#pragma unroll
        for (int ks = 0; ks < 2; ks++) {
            const int kk = ks * 16;
            uint32_t a[2][4], b[4][4];
#pragma unroll
            for (int mi = 0; mi < 2; mi++)
                ldsm4(a[mi][0], a[mi][1], a[mi][2], a[mi][3],
                      As_u + (uint32_t)((arow_l + mi * 16) * LD + kk + acol_l) * 2u);
#pragma unroll
            for (int nb = 0; nb < 4; nb++)
                ldsm4(b[nb][0], b[nb][1], b[nb][2], b[nb][3],
                      Bs_u + (uint32_t)((brow_l + nb * 16) * LD + kk + bcol_l) * 2u);
#pragma unroll
            for (int mi = 0; mi < 2; mi++)
#pragma unroll
                for (int nb = 0; nb < 4; nb++) {
                    mma16n8k16h(acc[mi][nb * 2 + 0], a[mi], &b[nb][0]);
                    mma16n8k16h(acc[mi][nb * 2 + 1], a[mi], &b[nb][2]);
                }
        }
    }

#pragma unroll
    for (int mi = 0; mi < 2; mi++) {
        const int row0 = bm + wm * 32 + mi * 16 + lq;
#pragma unroll
        for (int ni = 0; ni < 8; ni++) {
            const int col = bn + wn * 64 + ni * 8 + lr * 2;
            const float bz0 = bias[col], bz1 = bias[col + 1];
            if (Cf) {
                if (row0 < M)
                    *reinterpret_cast<float2*>(Cf + (size_t)row0 * N + col) =
                        make_float2(acc[mi][ni][0] + bz0, acc[mi][ni][1] + bz1);
                if (row0 + 8 < M)
                    *reinterpret_cast<float2*>(Cf + (size_t)(row0 + 8) * N + col) =
                        make_float2(acc[mi][ni][2] + bz0, acc[mi][ni][3] + bz1);
            } else {
                if (row0 < M)
                    *reinterpret_cast<__half2*>(Ch + (size_t)row0 * N + col) =
                        __floats2half2_rn(acc[mi][ni][0] + bz0, acc[mi][ni][1] + bz1);
                if (row0 + 8 < M)
                    *reinterpret_cast<__half2*>(Ch + (size_t)(row0 + 8) * N + col) =
                        __floats2half2_rn(acc[mi][ni][2] + bz0, acc[mi][ni][3] + bz1);
            }
        }
    }
}

// ============ fp32-A GEMM body: cp.async fp32 staging (3-deep) + smem cvt -> fp16 tile ============
// smem bytes: A16[2] @ 0,10240 ; B16[3] @ 20480+10240*s ; STG[3] @ 51200+18432*s  (end 106496)
__device__ __forceinline__ void gemm_body_f32a(const float* __restrict__ A,
                                               const __half* __restrict__ B,
                                               const float* __restrict__ bias,
                                               __half* __restrict__ Ch, int bn, int M) {
    constexpr int BK = 32, LDH = 40, LDF = 36;
    constexpr int NCHUNK = DMOD / BK;

    extern __shared__ __half smh[];
    char* sbase = reinterpret_cast<char*>(smh);
    const uint32_t su = (uint32_t)__cvta_generic_to_shared(smh);

    const int tid = threadIdx.x;
    const int wid = tid >> 5;
    const int lane = tid & 31;
    const int wm = wid & 3;
    const int wn = wid >> 2;
    const int bm = blockIdx.y * 128;
    const int lq = lane >> 2;
    const int lr = lane & 3;

    const int arow_l = wm * 32 + (lane & 15);
    const int acol_l = (lane >> 4) << 3;
    const int brow_l = wn * 64 + (lane & 7) + ((lane >> 4) << 3);
    const int bcol_l = ((lane >> 3) & 1) << 3;

    auto issue = [&](int cc) {
        const int k0 = cc * BK;
        const int s = cc % 3;
        const uint32_t stg_u = su + 51200u + (uint32_t)(s * 18432);
        const uint32_t b_u = su + 20480u + (uint32_t)(s * 10240);
#pragma unroll
        for (int i = 0; i < 4; i++) {
            int u = tid + i * 256;
            int row = u >> 3, f4 = (u & 7) * 4;
            int gr = bm + row;
            uint32_t sz = gr < M ? 16u : 0u;
            gr = gr < M ? gr : M - 1;
            cp_async16(stg_u + (uint32_t)(row * LDF + f4) * 4u,
                       A + (size_t)gr * DMOD + k0 + f4, sz);
        }
#pragma unroll
        for (int i = 0; i < 2; i++) {
            int u = tid + i * 256;
            int row = u >> 2, f8 = (u & 3) * 8;
            cp_async16(b_u + (uint32_t)(row * LDH + f8) * 2u,
                       B + (size_t)(bn + row) * DMOD + k0 + f8, 16u);
        }
        cp_commit();
    };

    float acc[2][8][4];
#pragma unroll
    for (int i = 0; i < 2; i++)
#pragma unroll
        for (int j = 0; j < 8; j++)
#pragma unroll
            for (int r = 0; r < 4; r++) acc[i][j][r] = 0.0f;

    issue(0);
    issue(1);

    for (int c = 0; c < NCHUNK; c++) {
        cp_wait1();
        __syncthreads();
        if (c + 2 < NCHUNK) issue(c + 2);

        // convert staged fp32 chunk c -> fp16 A tile (c&1)
        {
            const float* stg = reinterpret_cast<const float*>(sbase + 51200 + (c % 3) * 18432);
            char* a16 = sbase + (c & 1) * 10240;
#pragma unroll
            for (int i = 0; i < 2; i++) {
                int u = tid + i * 256;
                int row = u >> 2, f8 = (u & 3) * 8;
                const float* p = stg + row * LDF + f8;
                float4 a0 = *reinterpret_cast<const float4*>(p);
                float4 a1 = *reinterpret_cast<const float4*>(p + 4);
                *reinterpret_cast<uint4*>(a16 + (row * LDH + f8) * 2) = pack8(a0, a1);
            }
        }
        __syncthreads();

        const uint32_t As_u = su + (uint32_t)((c & 1) * 10240);
        const uint32_t Bs_u = su + 20480u + (uint32_t)((c % 3) * 10240);
#pragma unroll
        for (int ks = 0; ks < 2; ks++) {
            const int kk = ks * 16;
            uint32_t a[2][4], b[4][4];
#pragma unroll
            for (int mi = 0; mi < 2; mi++)
                ldsm4(a[mi][0], a[mi][1], a[mi][2], a[mi][3],
                      As_u + (uint32_t)((arow_l + mi * 16) * LDH + kk + acol_l) * 2u);
#pragma unroll
            for (int nb = 0; nb < 4; nb++)
                ldsm4(b[nb][0], b[nb][1], b[nb][2], b[nb][3],
                      Bs_u + (uint32_t)((brow_l + nb * 16) * LDH + kk + bcol_l) * 2u);
#pragma unroll
            for (int mi = 0; mi < 2; mi++)
#pragma unroll
                for (int nb = 0; nb < 4; nb++) {
                    mma16n8k16h(acc[mi][nb * 2 + 0], a[mi], &b[nb][0]);
                    mma16n8k16h(acc[mi][nb * 2 + 1], a[mi], &b[nb][2]);
                }
        }
    }

#pragma unroll
    for (int mi = 0; mi < 2; mi++) {
        const int row0 = bm + wm * 32 + mi * 16 + lq;
#pragma unroll
        for (int ni = 0; ni < 8; ni++) {
            const int col = bn + wn * 64 + ni * 8 + lr * 2;
            const float bz0 = bias[col], bz1 = bias[col + 1];
            if (row0 < M)
                *reinterpret_cast<__half2*>(Ch + (size_t)row0 * DMOD + col) =
                    __floats2half2_rn(acc[mi][ni][0] + bz0, acc[mi][ni][1] + bz1);
            if (row0 + 8 < M)
                *reinterpret_cast<__half2*>(Ch + (size_t)(row0 + 8) * DMOD + col) =
                    __floats2half2_rn(acc[mi][ni][2] + bz0, acc[mi][ni][3] + bz1);
        }
    }
}

// ============ oa GEMM body: fp32 q/qpos via cp.async staging, fused add+cvt ============
// smem bytes: A tile fp16 [0,10240); B stages [10240,30720); q [30720,49152); qpos [49152,67584)
__device__ __forceinline__ void gemm_body_oa(const float* __restrict__ q,
                                             const float* __restrict__ qp) {
    constexpr int BK = 32, LDH = 40, LDF = 36;
    constexpr int NCHUNK = DMOD / BK;

    extern __shared__ __half smh[];
    char* sbase = reinterpret_cast<char*>(smh);
    const uint32_t su = (uint32_t)__cvta_generic_to_shared(smh);
    const uint32_t A_u = su;
    const uint32_t B_u = su + 10240;
    const uint32_t QF_u = su + 30720;
    const uint32_t QP_u = su + 49152;

    const int tid = threadIdx.x;
    const int wid = tid >> 5;
    const int lane = tid & 31;
    const int wm = wid & 3;
    const int wn = wid >> 2;
    const int bm = blockIdx.y * 128;
    const int lq = lane >> 2;
    const int lr = lane & 3;

    const int arow_l = wm * 32 + (lane & 15);
    const int acol_l = (lane >> 4) << 3;
    const int brow_l = wn * 64 + (lane & 7) + ((lane >> 4) << 3);
    const int bcol_l = ((lane >> 3) & 1) << 3;

    auto issue_chunk = [&](int k0, int bbuf) {
#pragma unroll
        for (int i = 0; i < 4; i++) {
            int idx = tid + i * 256;
            int row = idx >> 3, f4 = (idx & 7) * 4;
            int gr = bm + row;
            uint32_t sz = gr < LQ ? 16u : 0u;
            gr = gr < LQ ? gr : LQ - 1;
            cp_async16(QF_u + (uint32_t)(row * LDF + f4) * 4u,
                       q + (size_t)gr * DMOD + k0 + f4, sz);
            cp_async16(QP_u + (uint32_t)(row * LDF + f4) * 4u,
                       qp + (size_t)gr * DMOD + k0 + f4, sz);
        }
#pragma unroll
        for (int i = 0; i < 2; i++) {
            int idx = tid + i * 256;
            int row = idx >> 2, f8 = (idx & 3) * 8;
            cp_async16(B_u + (uint32_t)(bbuf * 10240) + (uint32_t)(row * LDH + f8) * 2u,
                       g_woa + (size_t)row * DMOD + k0 + f8, 16u);
        }
        cp_commit();
    };

    float acc[2][8][4];
#pragma unroll
    for (int i = 0; i < 2; i++)
#pragma unroll
        for (int j = 0; j < 8; j++)
#pragma unroll
            for (int r = 0; r < 4; r++) acc[i][j][r] = 0.0f;

    issue_chunk(0, 0);

    for (int c = 0; c < NCHUNK; c++) {
        cp_wait0();
        __syncthreads();
        const float* qf = reinterpret_cast<const float*>(sbase + 30720);
        const float* qpf = reinterpret_cast<const float*>(sbase + 49152);
#pragma unroll
        for (int i = 0; i < 2; i++) {
            int g = tid + i * 256;
            int row = g >> 2, f8 = (g & 3) * 8;
            const float* a = qf + row * LDF + f8;
            const float* b = qpf + row * LDF + f8;
            float4 a0 = *reinterpret_cast<const float4*>(a);
            float4 a1 = *reinterpret_cast<const float4*>(a + 4);
            float4 b0 = *reinterpret_cast<const float4*>(b);
            float4 b1 = *reinterpret_cast<const float4*>(b + 4);
            a0.x += b0.x; a0.y += b0.y; a0.z += b0.z; a0.w += b0.w;
            a1.x += b1.x; a1.y += b1.y; a1.z += b1.z; a1.w += b1.w;
            *reinterpret_cast<uint4*>(sbase + (row * LDH + f8) * 2) = pack8(a0, a1);
        }
        __syncthreads();
        if (c + 1 < NCHUNK) issue_chunk((c + 1) * BK, (c + 1) & 1);

        const uint32_t Bs_u = B_u + (uint32_t)((c & 1) * 10240);
#pragma unroll
        for (int ks = 0; ks < 2; ks++) {
            const int kk = ks * 16;
            uint32_t a[2][4], b[4][4];
#pragma unroll
            for (int mi = 0; mi < 2; mi++)
                ldsm4(a[mi][0], a[mi][1], a[mi][2], a[mi][3],
                      A_u + (uint32_t)((arow_l + mi * 16) * LDH + kk + acol_l) * 2u);
#pragma unroll
            for (int nb = 0; nb < 4; nb++)
                ldsm4(b[nb][0], b[nb][1], b[nb][2], b[nb][3],
                      Bs_u + (uint32_t)((brow_l + nb * 16) * LDH + kk + bcol_l) * 2u);
#pragma unroll
            for (int mi = 0; mi < 2; mi++)
#pragma unroll
                for (int nb = 0; nb < 4; nb++) {
                    mma16n8k16h(acc[mi][nb * 2 + 0], a[mi], &b[nb][0]);
                    mma16n8k16h(acc[mi][nb * 2 + 1], a[mi], &b[nb][2]);
                }
        }
    }

#pragma unroll
    for (int mi = 0; mi < 2; mi++) {
        const int row0 = bm + wm * 32 + mi * 16 + lq;
#pragma unroll
        for (int ni = 0; ni < 8; ni++) {
            const int col = wn * 64 + ni * 8 + lr * 2;
            const float bz0 = g_boa[col], bz1 = g_boa[col + 1];
            if (row0 < LQ)
                *reinterpret_cast<float2*>(g_oa + (size_t)row0 * 128 + col) =
                    make_float2(acc[mi][ni][0] + bz0, acc[mi][ni][1] + bz1);
            if (row0 + 8 < LQ)
                *reinterpret_cast<float2*>(g_oa + (size_t)(row0 + 8) * 128 + col) =
                    make_float2(acc[mi][ni][2] + bz0, acc[mi][ni][3] + bz1);
        }
    }
}

// ---- fused value + oa GEMM: x<2 -> value tiles (fp32 A direct), x==2 -> oa ----
__global__ __launch_bounds__(256, 2)
void valoa_gemm(const float* __restrict__ inp, const float* __restrict__ bv,
                const float* __restrict__ q, const float* __restrict__ qp) {
    if (blockIdx.x < 2)
        gemm_body_f32a(inp, g_wv, bv, g_value, blockIdx.x * 128, LQ);
    else
        gemm_body_oa(q, qp);
}

// ---- output GEMM ----
__global__ __launch_bounds__(256, 2)
void out_gemm(const float* __restrict__ bout, float* __restrict__ out) {
    gemm_body(g_sampled, g_wout, bout, nullptr, out, blockIdx.x * 128, DMOD, LQ);
}

// ---------------- sampler: scalar phase + dual-head half2 gather ----------------
__global__ __launch_bounds__(256)
void sample_kernel(const float* __restrict__ refpts) {
    __shared__ int2 s_pc[256 * 4];

    const int tid = threadIdx.x;
    const int q0 = blockIdx.x * GQ;
    const int qi = tid >> 5;
    const int h = (tid >> 2) & 7;
    const int p = tid & 3;
    const int q = q0 + qi;

    const float refx = refpts[q * 2 + 0];
    const float refy = refpts[q * 2 + 1];
    const float* row = g_oa + (size_t)q * 128;
    const float lg = row[64 + h * 4 + p];
    const float ox = row[h * 8 + p * 2 + 0];
    const float oy = row[h * 8 + p * 2 + 1];

    float mx = lg;
    mx = fmaxf(mx, __shfl_xor_sync(0xFFFFFFFFu, mx, 1));
    mx = fmaxf(mx, __shfl_xor_sync(0xFFFFFFFFu, mx, 2));
    float e = expf(lg - mx);
    float s = e;
    s += __shfl_xor_sync(0xFFFFFFFFu, s, 1);
    s += __shfl_xor_sync(0xFFFFFFFFu, s, 2);
    const float ap = e / s;

    const float x = (refx + ox * (1.0f / WSP)) * WSP - 0.5f;
    const float y = (refy + oy * (1.0f / HSP)) * HSP - 0.5f;
    const float x0f = floorf(x), y0f = floorf(y);
    const int x0 = (int)x0f, y0 = (int)y0f;
    const float lw = x - x0f, lh = y - y0f;
    const int x1 = x0 + 1, y1 = y0 + 1;

    const float wc[4] = { (1.0f - lh) * (1.0f - lw), (1.0f - lh) * lw,
                          lh * (1.0f - lw),          lh * lw };
    const int xs[4] = { x0, x1, x0, x1 };
    const int ys[4] = { y0, y0, y1, y1 };
#pragma unroll
    for (int c = 0; c < 4; c++) {
        const bool v = (xs[c] >= 0) & (xs[c] < WSP) & (ys[c] >= 0) & (ys[c] < HSP);
        const float w = v ? ap * wc[c] : 0.0f;
        const int idx = v ? (ys[c] * WSP + xs[c]) : 0;
        s_pc[tid * 4 + c] = make_int2(idx, __float_as_int(w));
    }
    __syncthreads();

    const int wid = tid >> 5, lane = tid & 31;
    const int half = lane >> 4;
    const int ci = lane & 15;
    const int gq = q0 + wid;

#pragma unroll
    for (int hh = 0; hh < 4; hh++) {
        const int head = hh * 2 + half;
        const __half2* vb = reinterpret_cast<const __half2*>(
            g_value + head * DH + ci * 2);
        const int sbase = (wid * 32 + head * 4) * 4;
        float ax = 0.0f, ay = 0.0f;
#pragma unroll
        for (int pc = 0; pc < 16; pc++) {
            int2 ew = s_pc[sbase + pc];
            const float w = __int_as_float(ew.y);
            float2 vf = __half22float2(vb[(size_t)ew.x * (DMOD / 2)]);
            ax += w * vf.x;
            ay += w * vf.y;
        }
        *reinterpret_cast<__half2*>(
            g_sampled + (size_t)gq * DMOD + head * DH + ci * 2) =
            __floats2half2_rn(ax, ay);
    }
}

// ---------------- launch ----------------
extern "C" void kernel_launch(void* const* d_in, const int* in_sizes, int n_in,
                              void* d_out, int out_size) {
    const float* query  = (const float*)d_in[0];
    const float* qpos   = (const float*)d_in[1];
    const float* refpts = (const float*)d_in[2];
    const float* inp    = (const float*)d_in[3];
    const float* Wv     = (const float*)d_in[4];
    const float* bv     = (const float*)d_in[5];
    const float* Woff   = (const float*)d_in[6];
    const float* boff   = (const float*)d_in[7];
    const float* Wattn  = (const float*)d_in[8];
    const float* battn  = (const float*)d_in[9];
    const float* Wout   = (const float*)d_in[10];
    const float* bout   = (const float*)d_in[11];
    float* out = (float*)d_out;

    const int gy = (LQ + 127) / 128;  // 313
    const int SMEM_VALOA = 106496;    // f32a body footprint (oa uses 67584 of it)
    const int SMEM_OUT = 4 * (2 * 128 * 40) * 2;  // 81920
    cudaFuncSetAttribute(valoa_gemm, cudaFuncAttributeMaxDynamicSharedMemorySize, SMEM_VALOA);
    cudaFuncSetAttribute(out_gemm,   cudaFuncAttributeMaxDynamicSharedMemorySize, SMEM_OUT);

    // 0. weights-only conversion (tiny)
    conv_w<<<(KB3 + 255) / 256, 256>>>(
        (const float4*)Wv, (const float4*)Wout,
        (const float4*)Woff, (const float4*)Wattn, boff, battn);

    // 1. fused: value projection (fp32 inp direct) + oa projection
    valoa_gemm<<<dim3(3, gy), 256, SMEM_VALOA>>>(inp, bv, query, qpos);

    // 2. fused softmax + bilinear sampling
    sample_kernel<<<LQ / GQ, 256>>>(refpts);

    // 3. out = sampled @ W_out^T + b_out
    out_gemm<<<dim3(2, gy), 256, SMEM_OUT>>>(bout, out);
}